// round 1
// baseline (speedup 1.0000x reference)
#include <cuda_runtime.h>
#include <math.h>

#define NB 2048
#define SL 64
#define NH 20
#define DKH 20
#define DEMB 300
#define HDIM 400
#define F1 200

// Global scratch for q|k|v per token: [B][L][1200] (cols 0-399=q, 400-799=k, 800-1199=v)
__device__ float g_qkv[(size_t)NB * SL * 3 * HDIM];

#define XS_PAD 301   // x rows: odd stride -> conflict-free
#define CTX_PAD 404  // ctx rows: 16B-aligned rows for float4 in phase C
#define QKV_PAD 24   // per-head q/k/v rows: 16B-aligned, 5 float4 per row
#define S_PAD 68     // scores rows: 16B-aligned

// dynamic smem layout:
//   region A: bytes [0, 77056)        x_s during GEMM; per-head bufs / pooling scratch after
//   region B: bytes [77056, 180480)   ctx [64][404] fp32
#define SMEM_BYTES 180480

__global__ __launch_bounds__(1024, 1)
void text_encoder_fused(const int*   __restrict__ text,
                        const float* __restrict__ emb,
                        const float* __restrict__ WQ, const float* __restrict__ bQ,
                        const float* __restrict__ WK, const float* __restrict__ bK,
                        const float* __restrict__ WV, const float* __restrict__ bV,
                        const float* __restrict__ W1, const float* __restrict__ b1,
                        const float* __restrict__ W2, const float* __restrict__ b2,
                        float* __restrict__ out)
{
    extern __shared__ char smem[];
    float* A   = (float*)smem;             // 77,056 B scratch region
    float* ctx = (float*)(smem + 77056);   // [64][404]
    const int tid = threadIdx.x;
    const int b   = blockIdx.x;

    // ---------------- Phase A: embedding gather -> x_s [64][301] ----------------
    float* xs = A;
    {
        const float4* emb4 = (const float4*)emb;  // 300 floats = 75 float4 per row
        for (int i = tid; i < SL * 75; i += 1024) {
            int l = i / 75, c = i % 75;
            int tok = text[b * SL + l];
            float4 v = emb4[(size_t)tok * 75 + c];
            float* row = xs + l * XS_PAD + c * 4;
            row[0] = v.x; row[1] = v.y; row[2] = v.z; row[3] = v.w;
        }
    }
    __syncthreads();

    // ---------------- Phase B1: QKV GEMM  [64,300] x [300,1200] -> g_qkv --------
    // tiles: 8 token-groups (8 tokens each) x 300 col-groups (4 cols each) = 2400
    {
        float* qg = g_qkv + (size_t)b * (SL * 3 * HDIM);
        for (int t = tid; t < 2400; t += 1024) {
            int tg = t / 300, cg = t % 300;
            int gc  = cg * 4;          // global col in [0,1200)
            int mat = gc / 400;        // 0=Q 1=K 2=V (tiles never cross: 400%4==0)
            int c   = gc - mat * 400;
            const float* W    = (mat == 0) ? WQ : (mat == 1) ? WK : WV;
            const float* bias = (mat == 0) ? bQ : (mat == 1) ? bK : bV;
            float4 bb = *(const float4*)(bias + c);
            float4 acc[8];
            #pragma unroll
            for (int r = 0; r < 8; r++) acc[r] = bb;
            const float* xrow = xs + (tg * 8) * XS_PAD;
            #pragma unroll 2
            for (int d = 0; d < DEMB; d++) {
                float4 w = *(const float4*)(W + d * 400 + c);
                #pragma unroll
                for (int r = 0; r < 8; r++) {
                    float xv = xrow[r * XS_PAD + d];
                    acc[r].x += xv * w.x; acc[r].y += xv * w.y;
                    acc[r].z += xv * w.z; acc[r].w += xv * w.w;
                }
            }
            #pragma unroll
            for (int r = 0; r < 8; r++) {
                int l = tg * 8 + r;
                *(float4*)(qg + (size_t)l * 1200 + gc) = acc[r];
            }
        }
    }
    __syncthreads();

    // ---------------- Phase B2: per-head attention -> ctx [64][400] -------------
    float* qh   = A;                       // [64][24]
    float* kh   = A + 64 * QKV_PAD;        // [64][24]
    float* vh   = A + 2 * 64 * QKV_PAD;    // [64][24]
    float* ss   = A + 3 * 64 * QKV_PAD;    // [64][68]
    float* rsum = ss + 64 * S_PAD;         // [64]
    const float* qg = g_qkv + (size_t)b * (SL * 3 * HDIM);

    for (int h = 0; h < NH; h++) {
        // load per-head slices q,k,v [64][20]
        for (int i = tid; i < 64 * 60; i += 1024) {
            int l = i / 60, c = i % 60;
            int m = c / 20, cc = c % 20;
            float v = qg[(size_t)l * 1200 + m * 400 + h * 20 + cc];
            float* dst = (m == 0) ? qh : (m == 1) ? kh : vh;
            dst[l * QKV_PAD + cc] = v;
        }
        __syncthreads();

        // scores: exp(q.k / sqrt(20))   (faithful unstable exp-softmax)
        for (int o = tid; o < 4096; o += 1024) {
            int lq = o >> 6, lk = o & 63;
            const float4* q4 = (const float4*)(qh + lq * QKV_PAD);
            const float4* k4 = (const float4*)(kh + lk * QKV_PAD);
            float acc = 0.f;
            #pragma unroll
            for (int j = 0; j < 5; j++) {
                float4 a = q4[j], kk = k4[j];
                acc += a.x * kk.x + a.y * kk.y + a.z * kk.z + a.w * kk.w;
            }
            ss[lq * S_PAD + lk] = expf(acc * 0.22360679774997896f); // 1/sqrt(20)
        }
        __syncthreads();

        // row sums (one warp per 2 rows)
        {
            int w = tid >> 5, lane = tid & 31;
            for (int row = w; row < 64; row += 32) {
                float v = ss[row * S_PAD + lane] + ss[row * S_PAD + lane + 32];
                #pragma unroll
                for (int off = 16; off; off >>= 1) v += __shfl_xor_sync(0xffffffffu, v, off);
                if (lane == 0) rsum[row] = v;
            }
        }
        __syncthreads();

        // ctx_h = (exp-scores @ v) / (rowsum + 1e-8)
        for (int o = tid; o < 1280; o += 1024) {
            int j = o % 20, lq = o / 20;
            float acc = 0.f;
            const float4* s4 = (const float4*)(ss + lq * S_PAD);
            #pragma unroll 4
            for (int lk4 = 0; lk4 < 16; lk4++) {
                float4 s = s4[lk4];
                int lk = lk4 * 4;
                acc += s.x * vh[(lk + 0) * QKV_PAD + j];
                acc += s.y * vh[(lk + 1) * QKV_PAD + j];
                acc += s.z * vh[(lk + 2) * QKV_PAD + j];
                acc += s.w * vh[(lk + 3) * QKV_PAD + j];
            }
            ctx[lq * CTX_PAD + h * 20 + j] = acc / (rsum[lq] + 1e-8f);
        }
        __syncthreads();
    }

    // ---------------- Phase C: additive pooling ----------------
    float* alpha = A;        // [64] accumulated logits
    float* wgt   = A + 64;   // [64] exp weights
    float* ssum  = A + 128;  // [1]
    if (tid < 64) alpha[tid] = 0.f;
    __syncthreads();

    // logit_l = sum_j tanh(ctx_l . W1[:,j] + b1_j) * W2_j
    // tiles: 100 col-pairs x 8 row-groups (8 rows each) = 800 threads
    if (tid < 800) {
        int jg = tid % 100, lb = tid / 100;
        int j0 = jg * 2;
        float acc0[8], acc1[8];
        float bj0 = b1[j0], bj1 = b1[j0 + 1];
        #pragma unroll
        for (int r = 0; r < 8; r++) { acc0[r] = bj0; acc1[r] = bj1; }
        const float* crow = ctx + (lb * 8) * CTX_PAD;
        #pragma unroll 2
        for (int d = 0; d < HDIM; d++) {
            float2 w = *(const float2*)(W1 + d * F1 + j0);
            #pragma unroll
            for (int r = 0; r < 8; r++) {
                float cv = crow[r * CTX_PAD + d];
                acc0[r] += cv * w.x; acc1[r] += cv * w.y;
            }
        }
        float w2a = W2[j0], w2b = W2[j0 + 1];
        #pragma unroll
        for (int r = 0; r < 8; r++) {
            float t = tanhf(acc0[r]) * w2a + tanhf(acc1[r]) * w2b;
            atomicAdd(&alpha[lb * 8 + r], t);
        }
    }
    __syncthreads();

    if (tid < 64) wgt[tid] = expf(alpha[tid] + b2[0]);
    __syncthreads();
    if (tid < 32) {
        float v = wgt[tid] + wgt[tid + 32];
        #pragma unroll
        for (int off = 16; off; off >>= 1) v += __shfl_xor_sync(0xffffffffu, v, off);
        if (tid == 0) ssum[0] = v;
    }
    __syncthreads();

    const float inv = 1.f / (ssum[0] + 1e-8f);
    for (int c = tid; c < HDIM; c += 1024) {
        float acc = 0.f;
        #pragma unroll 4
        for (int l = 0; l < 64; l++) acc += ctx[l * CTX_PAD + c] * wgt[l];
        out[(size_t)b * HDIM + c] = acc * inv;
    }
}

extern "C" void kernel_launch(void* const* d_in, const int* in_sizes, int n_in,
                              void* d_out, int out_size) {
    const int*   text = (const int*)  d_in[0];
    const float* emb  = (const float*)d_in[1];
    const float* WQ   = (const float*)d_in[2];
    const float* bQ   = (const float*)d_in[3];
    const float* WK   = (const float*)d_in[4];
    const float* bK   = (const float*)d_in[5];
    const float* WV   = (const float*)d_in[6];
    const float* bV   = (const float*)d_in[7];
    const float* W1   = (const float*)d_in[8];
    const float* b1   = (const float*)d_in[9];
    const float* W2   = (const float*)d_in[10];
    const float* b2   = (const float*)d_in[11];
    float* out = (float*)d_out;

    cudaFuncSetAttribute(text_encoder_fused,
                         cudaFuncAttributeMaxDynamicSharedMemorySize, SMEM_BYTES);
    text_encoder_fused<<<NB, 1024, SMEM_BYTES>>>(
        text, emb, WQ, bQ, WK, bK, WV, bV, W1, b1, W2, b2, out);
}

// round 3
// speedup vs baseline: 1.5071x; 1.5071x over previous
#include <cuda_runtime.h>
#include <cuda_bf16.h>
#include <cstdint>
#include <math.h>

#define NB 2048
#define SL 64
#define NH 20
#define DEMB 300
#define HDIM 400
#define F1 200

// ---------------------------------------------------------------------------
// Global scratch
// ---------------------------------------------------------------------------
// Packed bf16 k-pair weights, transposed: [1200 cols][160 k-pairs] as uint32
__device__ uint32_t g_Bhi[1200 * 160];
__device__ uint32_t g_Blo[1200 * 160];
// QKV output, layout [batch-pair][col 0..1199][token 0..127]
__device__ float g_qkv2[(size_t)(NB / 2) * 1200 * 128];

__device__ __forceinline__ uint32_t pack_bf16(float a, float b) {
    __nv_bfloat162 t = __floats2bfloat162_rn(a, b);
    return *(uint32_t*)&t;
}
__device__ __forceinline__ uint32_t smem_u32(const void* p) {
    uint32_t a;
    asm("{ .reg .u64 t; cvta.to.shared.u64 t, %1; cvt.u32.u64 %0, t; }" : "=r"(a) : "l"(p));
    return a;
}
__device__ __forceinline__ void cp_async16(uint32_t dst, const void* src) {
    asm volatile("cp.async.cg.shared.global [%0], [%1], 16;" :: "r"(dst), "l"(src) : "memory");
}
#define CP_COMMIT() asm volatile("cp.async.commit_group;" ::: "memory")
#define CP_WAIT1()  asm volatile("cp.async.wait_group 1;" ::: "memory")
#define CP_WAIT0()  asm volatile("cp.async.wait_group 0;" ::: "memory")

__device__ __forceinline__ void mma16816(float* d, const uint32_t* a, uint32_t b0, uint32_t b1) {
    asm volatile(
        "mma.sync.aligned.m16n8k16.row.col.f32.bf16.bf16.f32 "
        "{%0,%1,%2,%3}, {%4,%5,%6,%7}, {%8,%9}, {%0,%1,%2,%3};"
        : "+f"(d[0]), "+f"(d[1]), "+f"(d[2]), "+f"(d[3])
        : "r"(a[0]), "r"(a[1]), "r"(a[2]), "r"(a[3]), "r"(b0), "r"(b1));
}

// ---------------------------------------------------------------------------
// Kernel 1: weight conversion  W[300,400]x3 -> g_Bhi/g_Blo [1200][160]
// ---------------------------------------------------------------------------
__global__ void convert_w(const float* __restrict__ WQ,
                          const float* __restrict__ WK,
                          const float* __restrict__ WV)
{
    int idx = blockIdx.x * 256 + threadIdx.x;
    if (idx >= 1200 * 160) return;
    int n = idx / 160, p = idx % 160;
    int mat = n / 400, col = n - mat * 400;
    const float* W = (mat == 0) ? WQ : (mat == 1) ? WK : WV;
    int k = 2 * p;
    float w0 = (k < DEMB) ? W[k * 400 + col] : 0.f;
    float w1 = (k + 1 < DEMB) ? W[(k + 1) * 400 + col] : 0.f;
    __nv_bfloat16 h0 = __float2bfloat16(w0);
    __nv_bfloat16 h1 = __float2bfloat16(w1);
    float l0 = w0 - __bfloat162float(h0);
    float l1 = w1 - __bfloat162float(h1);
    g_Bhi[n * 160 + p] = pack_bf16(__bfloat162float(h0), __bfloat162float(h1));
    g_Blo[n * 160 + p] = pack_bf16(l0, l1);
}

// ---------------------------------------------------------------------------
// Kernel 2: QKV GEMM via mma.sync bf16 3-product split
//   grid = 1024 (one CTA = 2 batch rows = 128 tokens), block = 256 (8 warps)
// ---------------------------------------------------------------------------
#define XW 164                 // padded row stride in uint32 words
// smem word offsets (GEMM phase)
#define GW_XHI   0             // [128][164] during x phase
#define GW_XLO   20992
#define GW_BUF0  0             // B double buffers overlay x after A-frag load
#define GW_BUF1  13120         // each buf = hi[40][164] + lo[40][164] = 13120 words
#define GW_SOUT  26240         // [40][132] floats = 5280 words
#define GW_BIAS  42000         // 1200 floats
#define SMEM_G   ((GW_BIAS + 1200) * 4)   // 172,800 bytes

__global__ __launch_bounds__(256, 1)
void gemm_qkv(const int*   __restrict__ text,
              const float* __restrict__ emb,
              const float* __restrict__ bQ,
              const float* __restrict__ bK,
              const float* __restrict__ bV)
{
    extern __shared__ uint32_t sg[];
    const int tid = threadIdx.x;
    const int lane = tid & 31;
    const int wid = tid >> 5;            // 0..7 = m16 row-group
    const int q = lane & 3;
    const int bp = blockIdx.x;

    float* bias_s = (float*)(sg + GW_BIAS);
    for (int i = tid; i < 400; i += 256) {
        bias_s[i] = bQ[i]; bias_s[400 + i] = bK[i]; bias_s[800 + i] = bV[i];
    }

    // ---- x gather + hi/lo bf16 split -> smem ----
    uint32_t* xhi = sg + GW_XHI;
    uint32_t* xlo = sg + GW_XLO;
    for (int i = tid; i < 128 * 14; i += 256) {       // zero K padding pairs 150..163
        int r = i / 14, w = 150 + i % 14;
        xhi[r * XW + w] = 0; xlo[r * XW + w] = 0;
    }
    {
        const float4* emb4 = (const float4*)emb;
        const int* trow = text + bp * 128;
        for (int i = tid; i < 128 * 75; i += 256) {
            int r = i / 75, c = i % 75;
            int tok = trow[r];
            float4 v = emb4[(size_t)tok * 75 + c];
            __nv_bfloat16 hx = __float2bfloat16(v.x), hy = __float2bfloat16(v.y);
            __nv_bfloat16 hz = __float2bfloat16(v.z), hw = __float2bfloat16(v.w);
            xhi[r * XW + 2 * c]     = pack_bf16(__bfloat162float(hx), __bfloat162float(hy));
            xhi[r * XW + 2 * c + 1] = pack_bf16(__bfloat162float(hz), __bfloat162float(hw));
            xlo[r * XW + 2 * c]     = pack_bf16(v.x - __bfloat162float(hx), v.y - __bfloat162float(hy));
            xlo[r * XW + 2 * c + 1] = pack_bf16(v.z - __bfloat162float(hz), v.w - __bfloat162float(hw));
        }
    }
    __syncthreads();

    // ---- load resident A fragments (per warp: its m16 row-group, all 20 ksteps) ----
    uint32_t ahi[20][4], alo[20][4];
    {
        const int r0 = wid * 16 + (lane >> 2);
        const int r1 = r0 + 8;
        #pragma unroll
        for (int kk = 0; kk < 20; kk++) {
            int w0 = 8 * kk + q;
            ahi[kk][0] = xhi[r0 * XW + w0];
            ahi[kk][1] = xhi[r1 * XW + w0];
            ahi[kk][2] = xhi[r0 * XW + w0 + 4];
            ahi[kk][3] = xhi[r1 * XW + w0 + 4];
            alo[kk][0] = xlo[r0 * XW + w0];
            alo[kk][1] = xlo[r1 * XW + w0];
            alo[kk][2] = xlo[r0 * XW + w0 + 4];
            alo[kk][3] = xlo[r1 * XW + w0 + 4];
        }
    }
    __syncthreads();   // x region now dead -> B buffers may overwrite

    // ---- B chunk prefetch helper (40 cols, hi+lo) ----
    auto prefetch = [&](int chunk, int bufw) {
        for (int i = tid; i < 3200; i += 256) {
            int arr = i >> 11;                    // 0..1 hmm 3200/2=1600: use i/1600
            arr = i / 1600;
            int j = i - arr * 1600;
            int col = j / 40, u = j % 40;
            const uint32_t* src = (arr ? g_Blo : g_Bhi) + (size_t)(chunk * 40 + col) * 160 + u * 4;
            uint32_t dst = smem_u32(sg + bufw + arr * 6560 + col * XW + u * 4);
            cp_async16(dst, src);
        }
        CP_COMMIT();
    };

    prefetch(0, GW_BUF0);

    float* gq = g_qkv2 + (size_t)bp * (1200 * 128);
    float* sout = (float*)(sg + GW_SOUT);

    for (int c = 0; c < 30; c++) {
        const int bufw = (c & 1) ? GW_BUF1 : GW_BUF0;
        if (c + 1 < 30) {
            prefetch(c + 1, (c & 1) ? GW_BUF0 : GW_BUF1);
            CP_WAIT1();
        } else {
            CP_WAIT0();
        }
        __syncthreads();

        const uint32_t* Bh = sg + bufw;
        const uint32_t* Bl = sg + bufw + 6560;
        const int r0 = wid * 16 + (lane >> 2);

        #pragma unroll
        for (int i = 0; i < 5; i++) {
            float acc[4] = {0.f, 0.f, 0.f, 0.f};
            const int nrow = i * 8 + (lane >> 2);
            #pragma unroll
            for (int kk = 0; kk < 20; kk++) {
                int w0 = 8 * kk + q;
                uint32_t bh0 = Bh[nrow * XW + w0];
                uint32_t bh1 = Bh[nrow * XW + w0 + 4];
                uint32_t bl0 = Bl[nrow * XW + w0];
                uint32_t bl1 = Bl[nrow * XW + w0 + 4];
                mma16816(acc, ahi[kk], bh0, bh1);
                mma16816(acc, alo[kk], bh0, bh1);
                mma16816(acc, ahi[kk], bl0, bl1);
            }
            // stage to sout [col_local 40][132]
            int cl = i * 8 + 2 * q;
            sout[cl * 132 + r0]           = acc[0];
            sout[(cl + 1) * 132 + r0]     = acc[1];
            sout[cl * 132 + r0 + 8]       = acc[2];
            sout[(cl + 1) * 132 + r0 + 8] = acc[3];
        }
        __syncthreads();

        // sout -> g_qkv2 [col][token], coalesced float4, + bias
        const float4* sout4 = (const float4*)sout;
        for (int i = tid; i < 40 * 32; i += 256) {
            int col = i >> 5, l4 = i & 31;
            float4 v = sout4[col * 33 + l4];
            float bb = bias_s[c * 40 + col];
            v.x += bb; v.y += bb; v.z += bb; v.w += bb;
            ((float4*)gq)[(c * 40 + col) * 32 + l4] = v;
        }
        __syncthreads();
    }
}

// ---------------------------------------------------------------------------
// Kernel 3: attention + pooling. grid = 2048 (1 batch row), block = 1024
// ---------------------------------------------------------------------------
#define S_PAD 68
#define CTX_PAD 404
// smem byte offsets
#define AO_Q    0          // [64][20] f32 = 5120
#define AO_K    5120
#define AO_V    10240
#define AO_SS   15360      // [64][68] = 17408
#define AO_RSUM 32768      // 64 floats
#define AO_CTX  33280      // [64][404] = 103424
#define SMEM_A  (AO_CTX + 64 * CTX_PAD * 4)   // 136,704

__global__ __launch_bounds__(1024, 1)
void attn_pool(const float* __restrict__ W1, const float* __restrict__ b1,
               const float* __restrict__ W2, const float* __restrict__ b2,
               float* __restrict__ out)
{
    extern __shared__ char sm[];
    const int tid = threadIdx.x;
    const int wid = tid >> 5;
    const int lane = tid & 31;
    const int b = blockIdx.x;
    const float* g2b = g_qkv2 + (size_t)(b >> 1) * (1200 * 128) + (b & 1) * 64;

    float* qs = (float*)(sm + AO_Q);
    float* ks = (float*)(sm + AO_K);
    float* vs = (float*)(sm + AO_V);
    float* ss = (float*)(sm + AO_SS);
    float* rsum = (float*)(sm + AO_RSUM);
    float* ctx = (float*)(sm + AO_CTX);

    for (int h = 0; h < NH; h++) {
        // coalesced per-head load: col (m,d) -> smem [l][20]
        for (int cc = wid; cc < 60; cc += 32) {
            int m = cc / 20, d = cc - m * 20;
            const float* src = g2b + (size_t)(m * 400 + h * 20 + d) * 128;
            float v0 = src[lane], v1 = src[lane + 32];
            float* dst = (m == 0) ? qs : (m == 1) ? ks : vs;
            dst[lane * 20 + d] = v0;
            dst[(lane + 32) * 20 + d] = v1;
        }
        __syncthreads();

        // scores = exp(q.k / sqrt(20))
        for (int o = tid; o < 4096; o += 1024) {
            int lq = o >> 6, lk = o & 63;
            const float4* q4 = (const float4*)(qs + lq * 20);
            const float4* k4 = (const float4*)(ks + lk * 20);
            float acc = 0.f;
            #pragma unroll
            for (int j = 0; j < 5; j++) {
                float4 a = q4[j], kk = k4[j];
                acc += a.x * kk.x + a.y * kk.y + a.z * kk.z + a.w * kk.w;
            }
            ss[lq * S_PAD + lk] = expf(acc * 0.22360679774997896f);
        }
        __syncthreads();

        // row sums
        {
            for (int row = wid; row < 64; row += 32) {
                float v = ss[row * S_PAD + lane] + ss[row * S_PAD + lane + 32];
                #pragma unroll
                for (int off = 16; off; off >>= 1) v += __shfl_xor_sync(0xffffffffu, v, off);
                if (lane == 0) rsum[row] = v;
            }
        }
        __syncthreads();

        // ctx_h = (scores @ v) / (rowsum + 1e-8)
        for (int o = tid; o < 1280; o += 1024) {
            int j = o % 20, lq = o / 20;
            float acc = 0.f;
            const float4* s4 = (const float4*)(ss + lq * S_PAD);
            #pragma unroll 4
            for (int lk4 = 0; lk4 < 16; lk4++) {
                float4 s = s4[lk4];
                int lk = lk4 * 4;
                acc += s.x * vs[(lk + 0) * 20 + j];
                acc += s.y * vs[(lk + 1) * 20 + j];
                acc += s.z * vs[(lk + 2) * 20 + j];
                acc += s.w * vs[(lk + 3) * 20 + j];
            }
            ctx[lq * CTX_PAD + h * 20 + j] = acc / (rsum[lq] + 1e-8f);
        }
        __syncthreads();
    }

    // ---- additive pooling ----
    float* alpha = (float*)sm;        // [64]
    float* wgt   = (float*)sm + 64;
    float* ssum  = (float*)sm + 128;
    if (tid < 64) alpha[tid] = 0.f;
    __syncthreads();

    if (tid < 800) {
        int jg = tid % 100, lb = tid / 100;
        int j0 = jg * 2;
        float acc0[8], acc1[8];
        float bj0 = b1[j0], bj1 = b1[j0 + 1];
        #pragma unroll
        for (int r = 0; r < 8; r++) { acc0[r] = bj0; acc1[r] = bj1; }
        const float* crow = ctx + (lb * 8) * CTX_PAD;
        #pragma unroll 2
        for (int d = 0; d < HDIM; d++) {
            float2 w = *(const float2*)(W1 + d * F1 + j0);
            #pragma unroll
            for (int r = 0; r < 8; r++) {
                float cv = crow[r * CTX_PAD + d];
                acc0[r] += cv * w.x; acc1[r] += cv * w.y;
            }
        }
        float w2a = W2[j0], w2b = W2[j0 + 1];
        #pragma unroll
        for (int r = 0; r < 8; r++) {
            float t = tanhf(acc0[r]) * w2a + tanhf(acc1[r]) * w2b;
            atomicAdd(&alpha[lb * 8 + r], t);
        }
    }
    __syncthreads();

    if (tid < 64) wgt[tid] = expf(alpha[tid] + b2[0]);
    __syncthreads();
    if (tid < 32) {
        float v = wgt[tid] + wgt[tid + 32];
        #pragma unroll
        for (int off = 16; off; off >>= 1) v += __shfl_xor_sync(0xffffffffu, v, off);
        if (tid == 0) ssum[0] = v;
    }
    __syncthreads();

    const float inv = 1.f / (ssum[0] + 1e-8f);
    for (int c = tid; c < HDIM; c += 1024) {
        float acc = 0.f;
        #pragma unroll 4
        for (int l = 0; l < 64; l++) acc += ctx[l * CTX_PAD + c] * wgt[l];
        out[(size_t)b * HDIM + c] = acc * inv;
    }
}

// ---------------------------------------------------------------------------
extern "C" void kernel_launch(void* const* d_in, const int* in_sizes, int n_in,
                              void* d_out, int out_size) {
    const int*   text = (const int*)  d_in[0];
    const float* emb  = (const float*)d_in[1];
    const float* WQ   = (const float*)d_in[2];
    const float* bQ   = (const float*)d_in[3];
    const float* WK   = (const float*)d_in[4];
    const float* bK   = (const float*)d_in[5];
    const float* WV   = (const float*)d_in[6];
    const float* bV   = (const float*)d_in[7];
    const float* W1   = (const float*)d_in[8];
    const float* b1   = (const float*)d_in[9];
    const float* W2   = (const float*)d_in[10];
    const float* b2   = (const float*)d_in[11];
    float* out = (float*)d_out;

    convert_w<<<(1200 * 160 + 255) / 256, 256>>>(WQ, WK, WV);

    cudaFuncSetAttribute(gemm_qkv, cudaFuncAttributeMaxDynamicSharedMemorySize, SMEM_G);
    gemm_qkv<<<NB / 2, 256, SMEM_G>>>(text, emb, bQ, bK, bV);

    cudaFuncSetAttribute(attn_pool, cudaFuncAttributeMaxDynamicSharedMemorySize, SMEM_A);
    attn_pool<<<NB, 1024, SMEM_A>>>(W1, b1, W2, b2, out);
}

// round 4
// speedup vs baseline: 1.8122x; 1.2024x over previous
#include <cuda_runtime.h>
#include <cuda_bf16.h>
#include <cstdint>
#include <math.h>

#define NB 2048
#define SL 64
#define NH 20
#define DEMB 300
#define HDIM 400
#define F1 200

// ---------------------------------------------------------------------------
// Global scratch
// ---------------------------------------------------------------------------
__device__ uint32_t g_Bhi[1200 * 160];     // QKV weights, packed bf16 kpairs, XOR-swizzled
__device__ uint32_t g_Blo[1200 * 160];
__device__ uint32_t g_W1hi[25 * 200 * 8];  // W1 fragments [kstep][col][pl^swz]
__device__ uint32_t g_W1lo[25 * 200 * 8];
__device__ float    g_qkv2[(size_t)(NB / 2) * 1200 * 128];   // [pair][col][token]
__device__ float    g_ctx[(size_t)NB * SL * HDIM];           // fp32 ctx rows
__device__ uint32_t g_ctxPhi[(size_t)(NB / 2) * 25 * 128 * 8]; // packed ctx frag
__device__ uint32_t g_ctxPlo[(size_t)(NB / 2) * 25 * 128 * 8];

__device__ __forceinline__ uint32_t pack_bf16(float a, float b) {
    __nv_bfloat162 t = __floats2bfloat162_rn(a, b);
    return *(uint32_t*)&t;
}
__device__ __forceinline__ uint32_t smem_u32(const void* p) {
    uint32_t a;
    asm("{ .reg .u64 t; cvta.to.shared.u64 t, %1; cvt.u32.u64 %0, t; }" : "=r"(a) : "l"(p));
    return a;
}
__device__ __forceinline__ void mma16816(float* d, const uint32_t* a, uint32_t b0, uint32_t b1) {
    asm volatile(
        "mma.sync.aligned.m16n8k16.row.col.f32.bf16.bf16.f32 "
        "{%0,%1,%2,%3}, {%4,%5,%6,%7}, {%8,%9}, {%0,%1,%2,%3};"
        : "+f"(d[0]), "+f"(d[1]), "+f"(d[2]), "+f"(d[3])
        : "r"(a[0]), "r"(a[1]), "r"(a[2]), "r"(a[3]), "r"(b0), "r"(b1));
}

#define MBARRIER_INIT(mbar, cnt) \
    asm volatile("mbarrier.init.shared.b64 [%0], %1;" :: "r"((uint32_t)(mbar)), "r"((uint32_t)(cnt)) : "memory")
#define MBARRIER_EXPECT_TX(mbar, tx) \
    asm volatile("mbarrier.arrive.expect_tx.shared.b64 _, [%0], %1;" :: "r"((uint32_t)(mbar)), "r"((uint32_t)(tx)) : "memory")
#define MBARRIER_WAIT_PARITY(mbar, par) do {                                     \
    uint32_t _m = (uint32_t)(mbar); uint32_t _p = (uint32_t)(par); uint32_t _d;  \
    asm volatile("{\n\t.reg .pred p;\n\t"                                        \
        "mbarrier.try_wait.parity.acquire.cta.shared::cta.b64 p, [%1], %2;\n\t"  \
        "selp.b32 %0, 1, 0, p;\n\t}" : "=r"(_d) : "r"(_m), "r"(_p) : "memory");  \
    if (!_d) {                                                                   \
        asm volatile("{\n\t.reg .pred P1;\n\t"                                   \
        "WAIT_LOOP_%=:\n\t"                                                      \
        "mbarrier.try_wait.parity.acquire.cta.shared::cta.b64 P1, [%0], %1, 0x989680;\n\t" \
        "@P1 bra.uni WAIT_DONE_%=;\n\t"                                          \
        "bra.uni WAIT_LOOP_%=;\n\t"                                              \
        "WAIT_DONE_%=:\n\t}" :: "r"(_m), "r"(_p) : "memory");                    \
    }                                                                            \
} while (0)
#define BULK_G2S(dst, src, bytes, bar)                                           \
    asm volatile("cp.async.bulk.shared::cluster.global.mbarrier::complete_tx::bytes [%0], [%1], %2, [%3];" \
        :: "r"((uint32_t)(dst)), "l"(src), "r"((uint32_t)(bytes)), "r"((uint32_t)(bar)) : "memory")

// ---------------------------------------------------------------------------
// Kernel 1: weight conversion (QKV weights + W1 fragments)
// ---------------------------------------------------------------------------
__global__ void convert_w(const float* __restrict__ WQ,
                          const float* __restrict__ WK,
                          const float* __restrict__ WV,
                          const float* __restrict__ W1)
{
    int idx = blockIdx.x * 256 + threadIdx.x;
    if (idx < 1200 * 160) {
        int n = idx / 160, p = idx % 160;
        int mat = n / 400, col = n - mat * 400;
        const float* W = (mat == 0) ? WQ : (mat == 1) ? WK : WV;
        int k = 2 * p;
        float w0 = (k < DEMB) ? W[k * 400 + col] : 0.f;
        float w1 = (k + 1 < DEMB) ? W[(k + 1) * 400 + col] : 0.f;
        __nv_bfloat16 h0 = __float2bfloat16(w0);
        __nv_bfloat16 h1 = __float2bfloat16(w1);
        int dst = n * 160 + (p ^ (4 * (n & 7)));
        g_Bhi[dst] = pack_bf16(__bfloat162float(h0), __bfloat162float(h1));
        g_Blo[dst] = pack_bf16(w0 - __bfloat162float(h0), w1 - __bfloat162float(h1));
    } else if (idx < 1200 * 160 + 200 * 200) {
        int j = idx - 1200 * 160;
        int col = j % 200, p = j / 200;            // p = kpair 0..199 (K=400)
        float w0 = W1[(2 * p) * 200 + col];
        float w1 = W1[(2 * p + 1) * 200 + col];
        __nv_bfloat16 h0 = __float2bfloat16(w0);
        __nv_bfloat16 h1 = __float2bfloat16(w1);
        int dst = (p >> 3) * 1600 + col * 8 + ((p & 7) ^ (4 * ((col >> 2) & 1)));
        g_W1hi[dst] = pack_bf16(__bfloat162float(h0), __bfloat162float(h1));
        g_W1lo[dst] = pack_bf16(w0 - __bfloat162float(h0), w1 - __bfloat162float(h1));
    }
}

// ---------------------------------------------------------------------------
// Kernel 2: QKV GEMM (mma.sync bf16 3-product, bulk-copy B)
// ---------------------------------------------------------------------------
#define XW 164
#define GW_BUF0 0
#define GW_BUF1 12800
#define GW_SOUT 25600
#define GW_XHI  0
#define GW_XLO  20992
#define GW_BIAS 42000
#define GW_MBAR 43204
#define SMEM_G  (43208 * 4)

__global__ __launch_bounds__(256, 1)
void gemm_qkv(const int*   __restrict__ text,
              const float* __restrict__ emb,
              const float* __restrict__ bQ,
              const float* __restrict__ bK,
              const float* __restrict__ bV)
{
    extern __shared__ uint32_t sg[];
    const uint32_t sbase = smem_u32(sg);
    const int tid = threadIdx.x;
    const int lane = tid & 31;
    const int wid = tid >> 5;
    const int q = lane & 3;
    const int bp = blockIdx.x;
    const uint32_t bar0 = sbase + GW_MBAR * 4;
    const uint32_t bar1 = bar0 + 8;

    if (tid == 0) { MBARRIER_INIT(bar0, 1); MBARRIER_INIT(bar1, 1); }

    float* bias_s = (float*)(sg + GW_BIAS);
    for (int i = tid; i < 400; i += 256) {
        bias_s[i] = bQ[i]; bias_s[400 + i] = bK[i]; bias_s[800 + i] = bV[i];
    }

    // ---- x gather + hi/lo bf16 split -> smem ----
    uint32_t* xhi = sg + GW_XHI;
    uint32_t* xlo = sg + GW_XLO;
    for (int i = tid; i < 128 * 14; i += 256) {
        int r = i / 14, w = 150 + i % 14;
        xhi[r * XW + w] = 0; xlo[r * XW + w] = 0;
    }
    {
        const float4* emb4 = (const float4*)emb;
        const int* trow = text + bp * 128;
        for (int i = tid; i < 128 * 75; i += 256) {
            int r = i / 75, c = i % 75;
            int tok = trow[r];
            float4 v = emb4[(size_t)tok * 75 + c];
            __nv_bfloat16 hx = __float2bfloat16(v.x), hy = __float2bfloat16(v.y);
            __nv_bfloat16 hz = __float2bfloat16(v.z), hw = __float2bfloat16(v.w);
            xhi[r * XW + 2 * c]     = pack_bf16(__bfloat162float(hx), __bfloat162float(hy));
            xhi[r * XW + 2 * c + 1] = pack_bf16(__bfloat162float(hz), __bfloat162float(hw));
            xlo[r * XW + 2 * c]     = pack_bf16(v.x - __bfloat162float(hx), v.y - __bfloat162float(hy));
            xlo[r * XW + 2 * c + 1] = pack_bf16(v.z - __bfloat162float(hz), v.w - __bfloat162float(hw));
        }
    }
    __syncthreads();

    // ---- resident A fragments ----
    uint32_t ahi[20][4], alo[20][4];
    {
        const int r0 = wid * 16 + (lane >> 2);
        const int r1 = r0 + 8;
        #pragma unroll
        for (int kk = 0; kk < 20; kk++) {
            int w0 = 8 * kk + q;
            ahi[kk][0] = xhi[r0 * XW + w0];
            ahi[kk][1] = xhi[r1 * XW + w0];
            ahi[kk][2] = xhi[r0 * XW + w0 + 4];
            ahi[kk][3] = xhi[r1 * XW + w0 + 4];
            alo[kk][0] = xlo[r0 * XW + w0];
            alo[kk][1] = xlo[r1 * XW + w0];
            alo[kk][2] = xlo[r0 * XW + w0 + 4];
            alo[kk][3] = xlo[r1 * XW + w0 + 4];
        }
    }
    __syncthreads();   // x region dead

    // bulk prefetch of one 40-col chunk (hi 25600B + lo 25600B)
    auto prefetch = [&](int chunk, uint32_t dstw, uint32_t bar) {
        MBARRIER_EXPECT_TX(bar, 51200);
        BULK_G2S(sbase + dstw * 4,         g_Bhi + chunk * 6400, 25600, bar);
        BULK_G2S(sbase + dstw * 4 + 25600, g_Blo + chunk * 6400, 25600, bar);
    };
    if (tid == 0) prefetch(0, GW_BUF0, bar0);

    float* gq = g_qkv2 + (size_t)bp * (1200 * 128);
    float* sout = (float*)(sg + GW_SOUT);
    const int key = (lane >> 2) << 2;   // XOR swizzle key (bits 2..4)

    for (int c = 0; c < 30; c++) {
        if (c + 1 < 30 && tid == 0)
            prefetch(c + 1, (c & 1) ? GW_BUF0 : GW_BUF1, (c & 1) ? bar0 : bar1);
        MBARRIER_WAIT_PARITY((c & 1) ? bar1 : bar0, (c >> 1) & 1);

        const uint32_t* Bh = sg + ((c & 1) ? GW_BUF1 : GW_BUF0);
        const uint32_t* Bl = Bh + 6400;
        const int r0 = wid * 16 + (lane >> 2);

        #pragma unroll
        for (int i = 0; i < 5; i++) {
            float acc[4] = {0.f, 0.f, 0.f, 0.f};
            const int base = (i * 8 + (lane >> 2)) * 160;
            #pragma unroll
            for (int kk = 0; kk < 20; kk++) {
                int w0 = (8 * kk + q) ^ key;
                uint32_t bh0 = Bh[base + w0];
                uint32_t bh1 = Bh[base + (w0 ^ 4)];
                uint32_t bl0 = Bl[base + w0];
                uint32_t bl1 = Bl[base + (w0 ^ 4)];
                mma16816(acc, ahi[kk], bh0, bh1);
                mma16816(acc, alo[kk], bh0, bh1);
                mma16816(acc, ahi[kk], bl0, bl1);
            }
            int cl = i * 8 + 2 * q;
            sout[cl * 132 + r0]           = acc[0];
            sout[(cl + 1) * 132 + r0]     = acc[1];
            sout[cl * 132 + r0 + 8]       = acc[2];
            sout[(cl + 1) * 132 + r0 + 8] = acc[3];
        }
        __syncthreads();

        const float4* sout4 = (const float4*)sout;
        for (int i = tid; i < 40 * 32; i += 256) {
            int col = i >> 5, l4 = i & 31;
            float4 v = sout4[col * 33 + l4];
            float bb = bias_s[c * 40 + col];
            v.x += bb; v.y += bb; v.z += bb; v.w += bb;
            ((float4*)gq)[(c * 40 + col) * 32 + l4] = v;
        }
        __syncthreads();
    }
}

// ---------------------------------------------------------------------------
// Kernel 3: attention (fp32) -> g_ctx + packed ctx fragments
// ---------------------------------------------------------------------------
#define S_PAD 68
#define CTX_PAD 404
#define AO_Q    0
#define AO_K    5120
#define AO_V    10240
#define AO_SS   15360
#define AO_RSUM 32768
#define AO_CTX  33280
#define SMEM_A  (AO_CTX + 64 * CTX_PAD * 4)

__global__ __launch_bounds__(1024, 1)
void attn_kernel()
{
    extern __shared__ char sm[];
    const int tid = threadIdx.x;
    const int wid = tid >> 5;
    const int lane = tid & 31;
    const int b = blockIdx.x;
    const float* g2b = g_qkv2 + (size_t)(b >> 1) * (1200 * 128) + (b & 1) * 64;

    float* qs = (float*)(sm + AO_Q);
    float* ks = (float*)(sm + AO_K);
    float* vs = (float*)(sm + AO_V);
    float* ss = (float*)(sm + AO_SS);
    float* rsum = (float*)(sm + AO_RSUM);
    float* ctx = (float*)(sm + AO_CTX);

    for (int h = 0; h < NH; h++) {
        for (int cc = wid; cc < 60; cc += 32) {
            int m = cc / 20, d = cc - m * 20;
            const float* src = g2b + (size_t)(m * 400 + h * 20 + d) * 128;
            float v0 = src[lane], v1 = src[lane + 32];
            float* dst = (m == 0) ? qs : (m == 1) ? ks : vs;
            dst[lane * 20 + d] = v0;
            dst[(lane + 32) * 20 + d] = v1;
        }
        __syncthreads();

        for (int o = tid; o < 4096; o += 1024) {
            int lq = o >> 6, lk = o & 63;
            const float4* q4 = (const float4*)(qs + lq * 20);
            const float4* k4 = (const float4*)(ks + lk * 20);
            float acc = 0.f;
            #pragma unroll
            for (int j = 0; j < 5; j++) {
                float4 a = q4[j], kk = k4[j];
                acc += a.x * kk.x + a.y * kk.y + a.z * kk.z + a.w * kk.w;
            }
            ss[lq * S_PAD + lk] = expf(acc * 0.22360679774997896f);
        }
        __syncthreads();

        for (int row = wid; row < 64; row += 32) {
            float v = ss[row * S_PAD + lane] + ss[row * S_PAD + lane + 32];
            #pragma unroll
            for (int off = 16; off; off >>= 1) v += __shfl_xor_sync(0xffffffffu, v, off);
            if (lane == 0) rsum[row] = v;
        }
        __syncthreads();

        for (int o = tid; o < 1280; o += 1024) {
            int j = o % 20, lq = o / 20;
            float acc = 0.f;
            const float4* s4 = (const float4*)(ss + lq * S_PAD);
            #pragma unroll 4
            for (int lk4 = 0; lk4 < 16; lk4++) {
                float4 s = s4[lk4];
                int lk = lk4 * 4;
                acc += s.x * vs[(lk + 0) * 20 + j];
                acc += s.y * vs[(lk + 1) * 20 + j];
                acc += s.z * vs[(lk + 2) * 20 + j];
                acc += s.w * vs[(lk + 3) * 20 + j];
            }
            ctx[lq * CTX_PAD + h * 20 + j] = acc / (rsum[lq] + 1e-8f);
        }
        __syncthreads();
    }

    // ---- emit ctx: fp32 rows + packed hi/lo fragments ----
    const float4* ctx4 = (const float4*)ctx;
    for (int i = tid; i < 6400; i += 1024) {
        int l = i / 100, c4 = i % 100;
        ((float4*)g_ctx)[((size_t)b * 64 + l) * 100 + c4] = ctx4[l * 101 + c4];
    }
    {
        const int grow_base = (b & 1) * 64;
        const size_t pb25 = (size_t)(b >> 1) * 25;
        for (int i = tid; i < 12800; i += 1024) {
            int l = i / 200, p = i % 200;
            float c0 = ctx[l * CTX_PAD + 2 * p];
            float c1 = ctx[l * CTX_PAD + 2 * p + 1];
            __nv_bfloat16 h0 = __float2bfloat16(c0);
            __nv_bfloat16 h1 = __float2bfloat16(c1);
            uint32_t hi = pack_bf16(__bfloat162float(h0), __bfloat162float(h1));
            uint32_t lo = pack_bf16(c0 - __bfloat162float(h0), c1 - __bfloat162float(h1));
            int grow = grow_base + l;
            int k = p >> 3;
            int pl = (p & 7) ^ (4 * ((grow >> 2) & 1));
            size_t dst = ((pb25 + k) * 128 + grow) * 8 + pl;
            g_ctxPhi[dst] = hi;
            g_ctxPlo[dst] = lo;
        }
    }
}

// ---------------------------------------------------------------------------
// Kernel 4: pooling (tensorized): E=tanh(ctx@W1+b1), alpha=exp(E@W2+b2), out
//   grid = 1024 (2 batch rows), block = 256 (8 warps)
// ---------------------------------------------------------------------------
#define PW_BUF0 0        // Ah[1024] Al[1024] Bh[1600] Bl[1600] = 5248 words
#define PW_BUF1 5248
#define PW_B1   10496
#define PW_W2   10696
#define PW_LOG  10896    // 128 logits, then exp weights
#define PW_SUM  11026    // 2 floats
#define PW_MBAR 11028
#define SMEM_P  (11032 * 4)

__global__ __launch_bounds__(256, 1)
void pool_kernel(const float* __restrict__ b1,
                 const float* __restrict__ W2, const float* __restrict__ b2,
                 float* __restrict__ out)
{
    extern __shared__ uint32_t sp[];
    const uint32_t sbase = smem_u32(sp);
    const int tid = threadIdx.x;
    const int lane = tid & 31;
    const int wid = tid >> 5;
    const int q = lane & 3;
    const int c8 = lane >> 2;            // 0..7
    const int key = c8 & 4;              // XOR swizzle key (0 or 4)
    const int bp = blockIdx.x;
    const uint32_t bar0 = sbase + PW_MBAR * 4;
    const uint32_t bar1 = bar0 + 8;

    if (tid == 0) { MBARRIER_INIT(bar0, 1); MBARRIER_INIT(bar1, 1); }
    float* b1s = (float*)(sp + PW_B1);
    float* w2s = (float*)(sp + PW_W2);
    if (tid < 200) { b1s[tid] = b1[tid]; w2s[tid] = W2[tid]; }
    __syncthreads();

    const size_t pb25 = (size_t)bp * 25;
    auto pprefetch = [&](int k, uint32_t dstw, uint32_t bar) {
        MBARRIER_EXPECT_TX(bar, 20992);
        uint32_t d = sbase + dstw * 4;
        BULK_G2S(d,         g_ctxPhi + (pb25 + k) * 1024, 4096, bar);
        BULK_G2S(d + 4096,  g_ctxPlo + (pb25 + k) * 1024, 4096, bar);
        BULK_G2S(d + 8192,  g_W1hi + k * 1600, 6400, bar);
        BULK_G2S(d + 14592, g_W1lo + k * 1600, 6400, bar);
    };
    if (tid == 0) pprefetch(0, PW_BUF0, bar0);

    float acc[100];
    #pragma unroll
    for (int i = 0; i < 100; i++) acc[i] = 0.f;

    const int q0 = q ^ key, q1 = q0 ^ 4;
    const int r0 = wid * 16 + c8;

    for (int k = 0; k < 25; k++) {
        if (k + 1 < 25 && tid == 0)
            pprefetch(k + 1, (k & 1) ? PW_BUF0 : PW_BUF1, (k & 1) ? bar0 : bar1);
        MBARRIER_WAIT_PARITY((k & 1) ? bar1 : bar0, (k >> 1) & 1);

        const uint32_t* Ah = sp + ((k & 1) ? PW_BUF1 : PW_BUF0);
        const uint32_t* Al = Ah + 1024;
        const uint32_t* Bh = Ah + 2048;
        const uint32_t* Bl = Ah + 3648;

        uint32_t fhi[4], flo[4];
        fhi[0] = Ah[r0 * 8 + q0]; fhi[1] = Ah[(r0 + 8) * 8 + q0];
        fhi[2] = Ah[r0 * 8 + q1]; fhi[3] = Ah[(r0 + 8) * 8 + q1];
        flo[0] = Al[r0 * 8 + q0]; flo[1] = Al[(r0 + 8) * 8 + q0];
        flo[2] = Al[r0 * 8 + q1]; flo[3] = Al[(r0 + 8) * 8 + q1];

        #pragma unroll
        for (int t = 0; t < 25; t++) {
            const int cb = (t * 8 + c8) * 8;
            uint32_t bh0 = Bh[cb + q0], bh1 = Bh[cb + q1];
            uint32_t bl0 = Bl[cb + q0], bl1 = Bl[cb + q1];
            mma16816(acc + t * 4, fhi, bh0, bh1);
            mma16816(acc + t * 4, flo, bh0, bh1);
            mma16816(acc + t * 4, fhi, bl0, bl1);
        }
        __syncthreads();   // buffer consumed; safe for reuse next-next iter
    }

    // ---- epilogue: logits per row ----
    float part0 = 0.f, part8 = 0.f;
    #pragma unroll
    for (int t = 0; t < 25; t++) {
        int c0 = t * 8 + 2 * q;
        part0 += tanhf(acc[t * 4 + 0] + b1s[c0])     * w2s[c0];
        part0 += tanhf(acc[t * 4 + 1] + b1s[c0 + 1]) * w2s[c0 + 1];
        part8 += tanhf(acc[t * 4 + 2] + b1s[c0])     * w2s[c0];
        part8 += tanhf(acc[t * 4 + 3] + b1s[c0 + 1]) * w2s[c0 + 1];
    }
    part0 += __shfl_xor_sync(0xffffffffu, part0, 1);
    part0 += __shfl_xor_sync(0xffffffffu, part0, 2);
    part8 += __shfl_xor_sync(0xffffffffu, part8, 1);
    part8 += __shfl_xor_sync(0xffffffffu, part8, 2);
    float* logit = (float*)(sp + PW_LOG);
    if (q == 0) { logit[r0] = part0; logit[r0 + 8] = part8; }
    __syncthreads();

    // exp weights + per-batch sums
    float b2v = b2[0];
    if (tid < 128) logit[tid] = expf(logit[tid] + b2v);
    __syncthreads();
    float* ssum = (float*)(sp + PW_SUM);
    if (wid < 2) {
        float v = logit[wid * 64 + lane] + logit[wid * 64 + lane + 32];
        #pragma unroll
        for (int off = 16; off; off >>= 1) v += __shfl_xor_sync(0xffffffffu, v, off);
        if (lane == 0) ssum[wid] = v;
    }
    __syncthreads();

    // weighted ctx sum per batch half
    for (int bh = 0; bh < 2; bh++) {
        if (tid < 200) {
            const float inv = 1.f / (ssum[bh] + 1e-8f);
            const float2* cr = (const float2*)g_ctx + ((size_t)(bp * 2 + bh) * 64) * 200 + tid;
            float2 a = make_float2(0.f, 0.f);
            #pragma unroll 4
            for (int l = 0; l < 64; l++) {
                float2 v = cr[l * 200];
                float w = logit[bh * 64 + l];
                a.x += w * v.x; a.y += w * v.y;
            }
            a.x *= inv; a.y *= inv;
            ((float2*)out)[(size_t)(bp * 2 + bh) * 200 + tid] = a;
        }
    }
}

// ---------------------------------------------------------------------------
extern "C" void kernel_launch(void* const* d_in, const int* in_sizes, int n_in,
                              void* d_out, int out_size) {
    const int*   text = (const int*)  d_in[0];
    const float* emb  = (const float*)d_in[1];
    const float* WQ   = (const float*)d_in[2];
    const float* bQ   = (const float*)d_in[3];
    const float* WK   = (const float*)d_in[4];
    const float* bK   = (const float*)d_in[5];
    const float* WV   = (const float*)d_in[6];
    const float* bV   = (const float*)d_in[7];
    const float* W1   = (const float*)d_in[8];
    const float* b1   = (const float*)d_in[9];
    const float* W2   = (const float*)d_in[10];
    const float* b2   = (const float*)d_in[11];
    float* out = (float*)d_out;

    convert_w<<<(1200 * 160 + 200 * 200 + 255) / 256, 256>>>(WQ, WK, WV, W1);

    cudaFuncSetAttribute(gemm_qkv, cudaFuncAttributeMaxDynamicSharedMemorySize, SMEM_G);
    gemm_qkv<<<NB / 2, 256, SMEM_G>>>(text, emb, bQ, bK, bV);

    cudaFuncSetAttribute(attn_kernel, cudaFuncAttributeMaxDynamicSharedMemorySize, SMEM_A);
    attn_kernel<<<NB, 1024, SMEM_A>>>();

    cudaFuncSetAttribute(pool_kernel, cudaFuncAttributeMaxDynamicSharedMemorySize, SMEM_P);
    pool_kernel<<<NB / 2, 256, SMEM_P>>>(b1, W2, b2, out);
}